// round 15
// baseline (speedup 1.0000x reference)
#include <cuda_runtime.h>
#include <cuda_bf16.h>
#include <math.h>
#include <stdint.h>

#define N_NODES  100000
#define N_EDGES  3200000
#define D_FEAT   128
#define HIDDEN   64
#define N_GRAPHS 64
#define N_CLASSES 10
#define NBLK     391   // ceil(N_NODES/256)

// ---------------- scratch (device globals; no allocation allowed) -----------
__device__ __align__(16) float g_dinv[N_NODES];
__device__ __align__(16) __nv_bfloat16 g_h[N_NODES * HIDDEN];   // h' = (X@W)*dinv
__device__ __align__(16) __nv_bfloat16 g_x2[N_NODES * HIDDEN];  // relu(agg1+b1)
__device__ __align__(16) float g_gsum[N_GRAPHS * HIDDEN];
// CSR scratch
__device__ int g_cnt[N_NODES];
__device__ int g_incl[N_NODES];
__device__ int g_bsum[NBLK];
__device__ int g_bsumx[NBLK];
__device__ int g_off[N_NODES + 1];
__device__ int g_cur[N_NODES];
__device__ __align__(16) int g_ssrc[N_EDGES];

// ---------------- zero + CSR build -------------------------------------------
__global__ void k_zero() {
    int i = blockIdx.x * blockDim.x + threadIdx.x;
    if (i < N_NODES) g_cnt[i] = 0;
    if (i < N_GRAPHS * HIDDEN) g_gsum[i] = 0.f;
}

// 4 edges per thread via int4
__global__ void k_hist(const int* __restrict__ dst) {
    int e4 = blockIdx.x * blockDim.x + threadIdx.x;
    if (e4 * 4 >= N_EDGES) return;
    int4 d = *reinterpret_cast<const int4*>(dst + e4 * 4);
    atomicAdd(&g_cnt[d.x], 1);
    atomicAdd(&g_cnt[d.y], 1);
    atomicAdd(&g_cnt[d.z], 1);
    atomicAdd(&g_cnt[d.w], 1);
}

// local inclusive scan per 256-block; also computes dinv (cnt already loaded)
__global__ void k_scan_local() {
    __shared__ int sm[256];
    int i = blockIdx.x * 256 + threadIdx.x;
    int v = (i < N_NODES) ? g_cnt[i] : 0;
    if (i < N_NODES) g_dinv[i] = rsqrtf((float)(v + 1));   // +1 self loop
    sm[threadIdx.x] = v;
    __syncthreads();
    #pragma unroll
    for (int ofs = 1; ofs < 256; ofs <<= 1) {
        int t = (threadIdx.x >= ofs) ? sm[threadIdx.x - ofs] : 0;
        __syncthreads();
        sm[threadIdx.x] += t;
        __syncthreads();
    }
    if (i < N_NODES) g_incl[i] = sm[threadIdx.x];
    if (threadIdx.x == 255) g_bsum[blockIdx.x] = sm[255];
}

__global__ void k_scan_blocks() {
    __shared__ int wsum[16];
    int t = threadIdx.x;
    int lane = t & 31, wid = t >> 5;
    int orig = (t < NBLK) ? g_bsum[t] : 0;
    int v = orig;
    #pragma unroll
    for (int ofs = 1; ofs < 32; ofs <<= 1) {
        int u = __shfl_up_sync(0xFFFFFFFFu, v, ofs);
        if (lane >= ofs) v += u;
    }
    if (lane == 31) wsum[wid] = v;
    __syncthreads();
    if (wid == 0) {
        int s = (lane < 16) ? wsum[lane] : 0;
        #pragma unroll
        for (int ofs = 1; ofs < 16; ofs <<= 1) {
            int u = __shfl_up_sync(0xFFFFFFFFu, s, ofs);
            if (lane >= ofs) s += u;
        }
        if (lane < 16) wsum[lane] = s;
    }
    __syncthreads();
    int add = (wid > 0) ? wsum[wid - 1] : 0;
    v += add;
    if (t < NBLK) g_bsumx[t] = v - orig;
    if (t == 0) g_off[N_NODES] = N_EDGES;
}

__global__ void k_finalize() {
    int i = blockIdx.x * blockDim.x + threadIdx.x;
    if (i >= N_NODES) return;
    int c = g_cnt[i];
    int o = g_bsumx[i >> 8] + g_incl[i] - c;
    g_off[i] = o;
    g_cur[i] = o;
}

// 4 edges per thread via int4
__global__ void k_fill(const int* __restrict__ src, const int* __restrict__ dst) {
    int e4 = blockIdx.x * blockDim.x + threadIdx.x;
    if (e4 * 4 >= N_EDGES) return;
    int4 s = *reinterpret_cast<const int4*>(src + e4 * 4);
    int4 d = *reinterpret_cast<const int4*>(dst + e4 * 4);
    g_ssrc[atomicAdd(&g_cur[d.x], 1)] = s.x;
    g_ssrc[atomicAdd(&g_cur[d.y], 1)] = s.y;
    g_ssrc[atomicAdd(&g_cur[d.z], 1)] = s.z;
    g_ssrc[atomicAdd(&g_cur[d.w], 1)] = s.w;
}

// ---------------- tensor-core GEMM -------------------------------------------
// h' = (X@W)*dinv[row], bf16 out. Single-stage: full X tile + full W staged
// once (max MLP on the DRAM stream), one barrier, sync-free MMA loop.
__device__ __forceinline__ void mma16816(float* c, const uint32_t* a, const uint32_t* b) {
    asm volatile(
        "mma.sync.aligned.m16n8k16.row.col.f32.bf16.bf16.f32 "
        "{%0,%1,%2,%3}, {%4,%5,%6,%7}, {%8,%9}, {%0,%1,%2,%3};"
        : "+f"(c[0]), "+f"(c[1]), "+f"(c[2]), "+f"(c[3])
        : "r"(a[0]), "r"(a[1]), "r"(a[2]), "r"(a[3]), "r"(b[0]), "r"(b[1]));
}

template <int K, typename TIN>
__global__ void __launch_bounds__(256)
k_gemm_tc(const TIN* __restrict__ X, const float* __restrict__ W,
          __nv_bfloat16* __restrict__ Hs) {
    constexpr int XS = K + 8;   // bf16 row stride: 136/72 -> conflict-free ldmatrix
    __shared__ __align__(16) __nv_bfloat16 Xs[128][XS];
    __shared__ __align__(16) __nv_bfloat16 Ws[K][72];

    const int t = threadIdx.x;
    const int lane = t & 31, wid = t >> 5;
    const int wm = (wid & 3) * 32;      // warp row base
    const int wn = (wid >> 2) * 32;     // warp col base
    const int row0 = blockIdx.x * 128;

    // stage full X tile (128 x K) as bf16, 16B-granularity loads
    if constexpr (sizeof(TIN) == 4) {
        #pragma unroll
        for (int i = t; i < 128 * (K / 4); i += 256) {
            int r = i / (K / 4), q = i % (K / 4);
            int gr = row0 + r;
            float4 xv = make_float4(0.f, 0.f, 0.f, 0.f);
            if (gr < N_NODES)
                xv = *reinterpret_cast<const float4*>(
                    &reinterpret_cast<const float*>(X)[(size_t)gr * K + q * 4]);
            __nv_bfloat162 lo = __float22bfloat162_rn(make_float2(xv.x, xv.y));
            __nv_bfloat162 hi = __float22bfloat162_rn(make_float2(xv.z, xv.w));
            uint2 st;
            st.x = *reinterpret_cast<unsigned*>(&lo);
            st.y = *reinterpret_cast<unsigned*>(&hi);
            *reinterpret_cast<uint2*>(&Xs[r][q * 4]) = st;
        }
    } else {
        #pragma unroll
        for (int i = t; i < 128 * (K / 8); i += 256) {
            int r = i / (K / 8), q = i % (K / 8);
            int gr = row0 + r;
            uint4 xv = make_uint4(0u, 0u, 0u, 0u);
            if (gr < N_NODES)
                xv = *reinterpret_cast<const uint4*>(
                    &reinterpret_cast<const __nv_bfloat16*>(X)[(size_t)gr * K + q * 8]);
            *reinterpret_cast<uint4*>(&Xs[r][q * 8]) = xv;
        }
    }
    // stage full W (K x 64), fp32 -> bf16
    #pragma unroll
    for (int i = t; i < K * 32; i += 256) {
        int k = i >> 5, n2 = i & 31;
        float2 wv = *reinterpret_cast<const float2*>(&W[(size_t)k * 64 + n2 * 2]);
        *reinterpret_cast<__nv_bfloat162*>(&Ws[k][n2 * 2]) = __float22bfloat162_rn(wv);
    }
    __syncthreads();

    float c[2][4][4] = {};

    #pragma unroll
    for (int ks = 0; ks < K / 16; ks++) {
        const int kk = ks * 16;
        uint32_t a[2][4], b[4][2];
        #pragma unroll
        for (int mi = 0; mi < 2; mi++) {
            uint32_t addr = (uint32_t)__cvta_generic_to_shared(
                &Xs[wm + mi * 16 + (lane & 15)][kk + (lane >> 4) * 8]);
            asm volatile("ldmatrix.sync.aligned.m8n8.x4.shared.b16 {%0,%1,%2,%3}, [%4];"
                : "=r"(a[mi][0]), "=r"(a[mi][1]), "=r"(a[mi][2]), "=r"(a[mi][3])
                : "r"(addr));
        }
        #pragma unroll
        for (int ni = 0; ni < 4; ni++) {
            uint32_t addr = (uint32_t)__cvta_generic_to_shared(
                &Ws[kk + (lane & 15)][wn + ni * 8]);
            asm volatile("ldmatrix.sync.aligned.m8n8.x2.trans.shared.b16 {%0,%1}, [%2];"
                : "=r"(b[ni][0]), "=r"(b[ni][1]) : "r"(addr));
        }
        #pragma unroll
        for (int mi = 0; mi < 2; mi++)
            #pragma unroll
            for (int ni = 0; ni < 4; ni++)
                mma16816(c[mi][ni], a[mi], b[ni]);
    }

    // epilogue: scale rows by dinv, convert to bf16, store pairs
    #pragma unroll
    for (int mi = 0; mi < 2; mi++) {
        int r0 = row0 + wm + mi * 16 + (lane >> 2);
        int r1 = r0 + 8;
        float dv0 = (r0 < N_NODES) ? g_dinv[r0] : 0.f;
        float dv1 = (r1 < N_NODES) ? g_dinv[r1] : 0.f;
        #pragma unroll
        for (int ni = 0; ni < 4; ni++) {
            int col = wn + ni * 8 + (lane & 3) * 2;
            if (r0 < N_NODES) {
                __nv_bfloat162 p = __float22bfloat162_rn(
                    make_float2(c[mi][ni][0] * dv0, c[mi][ni][1] * dv0));
                *reinterpret_cast<__nv_bfloat162*>(&Hs[(size_t)r0 * 64 + col]) = p;
            }
            if (r1 < N_NODES) {
                __nv_bfloat162 p = __float22bfloat162_rn(
                    make_float2(c[mi][ni][2] * dv1, c[mi][ni][3] * dv1));
                *reinterpret_cast<__nv_bfloat162*>(&Hs[(size_t)r1 * 64 + col]) = p;
            }
        }
    }
}

// ---------------- pull aggregation helpers -----------------------------------
__device__ __forceinline__ void acc_bf8(float* a, uint4 v) {
    float2 f;
    f = __bfloat1622float2(*reinterpret_cast<__nv_bfloat162*>(&v.x)); a[0] += f.x; a[1] += f.y;
    f = __bfloat1622float2(*reinterpret_cast<__nv_bfloat162*>(&v.y)); a[2] += f.x; a[3] += f.y;
    f = __bfloat1622float2(*reinterpret_cast<__nv_bfloat162*>(&v.z)); a[4] += f.x; a[5] += f.y;
    f = __bfloat1622float2(*reinterpret_cast<__nv_bfloat162*>(&v.w)); a[6] += f.x; a[7] += f.y;
}

__device__ __forceinline__ uint4 hadd2x4(uint4 x, uint4 y) {
    uint4 r;
    __nv_bfloat162 h;
    h = __hadd2(*reinterpret_cast<__nv_bfloat162*>(&x.x),
                *reinterpret_cast<__nv_bfloat162*>(&y.x));
    r.x = *reinterpret_cast<unsigned*>(&h);
    h = __hadd2(*reinterpret_cast<__nv_bfloat162*>(&x.y),
                *reinterpret_cast<__nv_bfloat162*>(&y.y));
    r.y = *reinterpret_cast<unsigned*>(&h);
    h = __hadd2(*reinterpret_cast<__nv_bfloat162*>(&x.z),
                *reinterpret_cast<__nv_bfloat162*>(&y.z));
    r.z = *reinterpret_cast<unsigned*>(&h);
    h = __hadd2(*reinterpret_cast<__nv_bfloat162*>(&x.w),
                *reinterpret_cast<__nv_bfloat162*>(&y.w));
    r.w = *reinterpret_cast<unsigned*>(&h);
    return r;
}

// 8 threads/node, shuffle-broadcast indices; pairwise bf16 add then fp32 acc.
__device__ __forceinline__ void gather_node(const uint4* hp, int node, int sub,
                                            int gbase, unsigned gmask, float* a) {
    int beg = g_off[node];
    int end = g_off[node + 1];
    acc_bf8(a, hp[(size_t)node * 8 + sub]);   // self term
    int j = beg;
    for (; j + 8 <= end; j += 8) {
        int idx = g_ssrc[j + sub];
        #pragma unroll
        for (int t = 0; t < 4; t++) {
            int s0 = __shfl_sync(gmask, idx, gbase + 2 * t, 32);
            int s1 = __shfl_sync(gmask, idx, gbase + 2 * t + 1, 32);
            uint4 v0 = hp[(size_t)s0 * 8 + sub];
            uint4 v1 = hp[(size_t)s1 * 8 + sub];
            acc_bf8(a, hadd2x4(v0, v1));      // one bf16 rounding per pair
        }
    }
    if (j < end) {
        int n8 = end - j;
        int idx = (sub < n8) ? g_ssrc[j + sub] : 0;
        #pragma unroll 7
        for (int t = 0; t < 7; t++) {
            if (t >= n8) break;
            int s = __shfl_sync(gmask, idx, gbase + t, 32);
            acc_bf8(a, hp[(size_t)s * 8 + sub]);
        }
    }
}

// layer-1 gather: x2 = relu(dinv[d]*(h'[d] + sum h'[src]) + b1), bf16 out
__global__ void k_gather_x2(const __nv_bfloat16* __restrict__ h,
                            const float* __restrict__ b1,
                            __nv_bfloat16* __restrict__ out) {
    int tid = blockIdx.x * blockDim.x + threadIdx.x;
    int node = tid >> 3;
    if (node >= N_NODES) return;
    const int lane = threadIdx.x & 31;
    const int sub = lane & 7;
    const int gbase = lane & 24;
    const unsigned gmask = 0xFFu << gbase;
    const uint4* hp = reinterpret_cast<const uint4*>(h);

    float a[8] = {};
    gather_node(hp, node, sub, gbase, gmask, a);

    float dv = g_dinv[node];
    float v[8];
    #pragma unroll
    for (int j = 0; j < 8; j++)
        v[j] = fmaxf(a[j] * dv + __ldg(&b1[sub * 8 + j]), 0.f);

    __nv_bfloat162 p0 = __float22bfloat162_rn(make_float2(v[0], v[1]));
    __nv_bfloat162 p1 = __float22bfloat162_rn(make_float2(v[2], v[3]));
    __nv_bfloat162 p2 = __float22bfloat162_rn(make_float2(v[4], v[5]));
    __nv_bfloat162 p3 = __float22bfloat162_rn(make_float2(v[6], v[7]));
    uint4 st;
    st.x = *reinterpret_cast<unsigned*>(&p0);
    st.y = *reinterpret_cast<unsigned*>(&p1);
    st.z = *reinterpret_cast<unsigned*>(&p2);
    st.w = *reinterpret_cast<unsigned*>(&p3);
    *reinterpret_cast<uint4*>(&out[(size_t)node * 64 + sub * 8]) = st;
}

// layer-2 gather fused with mean-pool accumulation
__global__ void k_gather_pool(const __nv_bfloat16* __restrict__ h,
                              const int* __restrict__ batch,
                              const float* __restrict__ b2) {
    __shared__ float sacc[8][64];
    int tid = blockIdx.x * blockDim.x + threadIdx.x;
    int node = tid >> 3;                       // 3125 full blocks x 32 nodes
    const int lane = threadIdx.x & 31;
    const int wid = threadIdx.x >> 5;
    const int sub = lane & 7;
    const int gbase = lane & 24;
    const unsigned gmask = 0xFFu << gbase;
    const uint4* hp = reinterpret_cast<const uint4*>(h);

    float a[8] = {};
    gather_node(hp, node, sub, gbase, gmask, a);

    float dv = g_dinv[node];
    float v[8];
    #pragma unroll
    for (int j = 0; j < 8; j++)
        v[j] = fmaxf(a[j] * dv + __ldg(&b2[sub * 8 + j]), 0.f);

    int n0 = node & ~31;
    int bt0 = batch[n0];
    bool uniform = (bt0 == batch[n0 + 31]);

    if (uniform) {
        #pragma unroll
        for (int j = 0; j < 8; j++) {
            v[j] += __shfl_xor_sync(0xFFFFFFFFu, v[j], 8);
            v[j] += __shfl_xor_sync(0xFFFFFFFFu, v[j], 16);
        }
        if (lane < 8) {
            #pragma unroll
            for (int j = 0; j < 8; j++) sacc[wid][lane * 8 + j] = v[j];
        }
        __syncthreads();
        if (threadIdx.x < 64) {
            float s = 0.f;
            #pragma unroll
            for (int w = 0; w < 8; w++) s += sacc[w][threadIdx.x];
            atomicAdd(&g_gsum[bt0 * 64 + threadIdx.x], s);
        }
    } else {
        int bt = batch[node];
        #pragma unroll
        for (int j = 0; j < 8; j++)
            atomicAdd(&g_gsum[bt * 64 + sub * 8 + j], v[j]);
        __syncthreads();   // keep barrier count uniform
    }
}

// ---------------- head --------------------------------------------------------
__global__ void k_head(const int* __restrict__ batch,
                       const float* __restrict__ linW, const float* __restrict__ linb,
                       float* __restrict__ out) {
    int g = threadIdx.x;
    if (g >= N_GRAPHS) return;
    int lo = 0, hi = N_NODES;
    while (lo < hi) { int m = (lo + hi) >> 1; if (batch[m] < g) lo = m + 1; else hi = m; }
    int s0 = lo;
    lo = s0; hi = N_NODES;
    while (lo < hi) { int m = (lo + hi) >> 1; if (batch[m] < g + 1) lo = m + 1; else hi = m; }
    float cnt = (float)(lo - s0);
    float inv = 1.0f / fmaxf(cnt, 1.0f);

    float logits[N_CLASSES];
#pragma unroll
    for (int c = 0; c < N_CLASSES; c++) logits[c] = linb[c];
    for (int f = 0; f < HIDDEN; f++) {
        float p = g_gsum[g * HIDDEN + f] * inv;
#pragma unroll
        for (int c = 0; c < N_CLASSES; c++) logits[c] += p * linW[f * N_CLASSES + c];
    }
    float m = logits[0];
#pragma unroll
    for (int c = 1; c < N_CLASSES; c++) m = fmaxf(m, logits[c]);
    float s = 0.f;
#pragma unroll
    for (int c = 0; c < N_CLASSES; c++) s += expf(logits[c] - m);
    float l = logf(s) + m;
#pragma unroll
    for (int c = 0; c < N_CLASSES; c++) out[g * N_CLASSES + c] = logits[c] - l;
}

// ---------------- launch ------------------------------------------------------
extern "C" void kernel_launch(void* const* d_in, const int* in_sizes, int n_in,
                              void* d_out, int out_size) {
    const float* x     = (const float*)d_in[0];
    const int*   ei    = (const int*)d_in[1];
    const int*   batch = (const int*)d_in[2];
    const float* W1    = (const float*)d_in[3];
    const float* b1    = (const float*)d_in[4];
    const float* W2    = (const float*)d_in[5];
    const float* b2    = (const float*)d_in[6];
    const float* linW  = (const float*)d_in[7];
    const float* linb  = (const float*)d_in[8];
    float* out = (float*)d_out;

    const int* src = ei;
    const int* dst = ei + N_EDGES;

    __nv_bfloat16 *p_h, *p_x2;
    cudaGetSymbolAddress((void**)&p_h, g_h);
    cudaGetSymbolAddress((void**)&p_x2, g_x2);

    const int NT = 256;
    const int edge4Blocks = (N_EDGES / 4 + NT - 1) / NT;
    const int gemmBlocks = (N_NODES + 127) / 128;
    const int gatherBlocks = (N_NODES * 8 + NT - 1) / NT;

    // fork-join: CSR tail (scan_blocks/finalize/fill) runs concurrently
    // with GEMM1 — they are data-independent. Host-only resources, created
    // and destroyed every call (nothing recorded at graph replay).
    cudaStream_t s2;
    cudaStreamCreateWithFlags(&s2, cudaStreamNonBlocking);
    cudaEvent_t evF, evJ;
    cudaEventCreateWithFlags(&evF, cudaEventDisableTiming);
    cudaEventCreateWithFlags(&evJ, cudaEventDisableTiming);

    k_zero<<<NBLK, NT>>>();
    k_hist<<<edge4Blocks, NT>>>(dst);
    k_scan_local<<<NBLK, 256>>>();                     // also computes dinv

    cudaEventRecord(evF, 0);
    cudaStreamWaitEvent(s2, evF, 0);
    k_scan_blocks<<<1, 512, 0, s2>>>();
    k_finalize<<<NBLK, NT, 0, s2>>>();
    k_fill<<<edge4Blocks, NT, 0, s2>>>(src, dst);
    cudaEventRecord(evJ, s2);

    k_gemm_tc<D_FEAT, float><<<gemmBlocks, NT>>>(x, W1, p_h);   // overlaps CSR tail

    cudaStreamWaitEvent(0, evJ, 0);                    // join before gather
    k_gather_x2<<<gatherBlocks, NT>>>(p_h, b1, p_x2);
    k_gemm_tc<HIDDEN, __nv_bfloat16><<<gemmBlocks, NT>>>(p_x2, W2, p_h);
    k_gather_pool<<<gatherBlocks, NT>>>(p_h, batch, b2);
    k_head<<<1, N_GRAPHS>>>(batch, linW, linb, out);

    cudaEventDestroy(evF);
    cudaEventDestroy(evJ);
    cudaStreamDestroy(s2);
}

// round 16
// speedup vs baseline: 1.0791x; 1.0791x over previous
#include <cuda_runtime.h>
#include <cuda_bf16.h>
#include <math.h>
#include <stdint.h>

#define N_NODES  100000
#define N_EDGES  3200000
#define D_FEAT   128
#define HIDDEN   64
#define N_GRAPHS 64
#define N_CLASSES 10
#define NBLK     391   // ceil(N_NODES/256)

// ---------------- scratch (device globals; no allocation allowed) -----------
__device__ __align__(16) float g_dinv[N_NODES];
__device__ __align__(16) __nv_bfloat16 g_h[N_NODES * HIDDEN];   // h' = (X@W)*dinv
__device__ __align__(16) __nv_bfloat16 g_x2[N_NODES * HIDDEN];  // relu(agg1+b1)
__device__ __align__(16) float g_gsum[N_GRAPHS * HIDDEN];
// CSR scratch
__device__ int g_cnt[N_NODES];
__device__ int g_incl[N_NODES];
__device__ int g_bsum[NBLK];
__device__ int g_off[N_NODES + 1];
__device__ int g_cur[N_NODES];
__device__ __align__(16) int g_ssrc[N_EDGES];

// ---------------- zero + CSR build -------------------------------------------
__global__ void k_zero() {
    int i = blockIdx.x * blockDim.x + threadIdx.x;
    if (i < N_NODES) g_cnt[i] = 0;
    if (i < N_GRAPHS * HIDDEN) g_gsum[i] = 0.f;
}

// 4 edges per thread via int4
__global__ void k_hist(const int* __restrict__ dst) {
    int e4 = blockIdx.x * blockDim.x + threadIdx.x;
    if (e4 * 4 >= N_EDGES) return;
    int4 d = *reinterpret_cast<const int4*>(dst + e4 * 4);
    atomicAdd(&g_cnt[d.x], 1);
    atomicAdd(&g_cnt[d.y], 1);
    atomicAdd(&g_cnt[d.z], 1);
    atomicAdd(&g_cnt[d.w], 1);
}

// local inclusive scan per 256-block; also computes dinv (cnt already loaded)
__global__ void k_scan_local() {
    __shared__ int sm[256];
    int i = blockIdx.x * 256 + threadIdx.x;
    int v = (i < N_NODES) ? g_cnt[i] : 0;
    if (i < N_NODES) g_dinv[i] = rsqrtf((float)(v + 1));   // +1 self loop
    sm[threadIdx.x] = v;
    __syncthreads();
    #pragma unroll
    for (int ofs = 1; ofs < 256; ofs <<= 1) {
        int t = (threadIdx.x >= ofs) ? sm[threadIdx.x - ofs] : 0;
        __syncthreads();
        sm[threadIdx.x] += t;
        __syncthreads();
    }
    if (i < N_NODES) g_incl[i] = sm[threadIdx.x];
    if (threadIdx.x == 255) g_bsum[blockIdx.x] = sm[255];
}

// offsets + cursors; each block reduces its own prefix of the 391 block sums
__global__ void k_finalize() {
    __shared__ int part[8];
    __shared__ int basesh;
    const int t = threadIdx.x;
    const int lane = t & 31, wid = t >> 5;
    const int b = blockIdx.x;

    int s = 0;
    for (int i = t; i < b; i += 256) s += g_bsum[i];
    #pragma unroll
    for (int o = 16; o; o >>= 1) s += __shfl_xor_sync(0xFFFFFFFFu, s, o);
    if (lane == 0) part[wid] = s;
    __syncthreads();
    if (t == 0) {
        int tot = 0;
        #pragma unroll
        for (int w = 0; w < 8; w++) tot += part[w];
        basesh = tot;
        if (b == 0) g_off[N_NODES] = N_EDGES;
    }
    __syncthreads();
    int base = basesh;

    int i = b * 256 + t;
    if (i >= N_NODES) return;
    int c = g_cnt[i];
    int o = base + g_incl[i] - c;   // exclusive global offset
    g_off[i] = o;
    g_cur[i] = o;
}

// 4 edges per thread via int4
__global__ void k_fill(const int* __restrict__ src, const int* __restrict__ dst) {
    int e4 = blockIdx.x * blockDim.x + threadIdx.x;
    if (e4 * 4 >= N_EDGES) return;
    int4 s = *reinterpret_cast<const int4*>(src + e4 * 4);
    int4 d = *reinterpret_cast<const int4*>(dst + e4 * 4);
    g_ssrc[atomicAdd(&g_cur[d.x], 1)] = s.x;
    g_ssrc[atomicAdd(&g_cur[d.y], 1)] = s.y;
    g_ssrc[atomicAdd(&g_cur[d.z], 1)] = s.z;
    g_ssrc[atomicAdd(&g_cur[d.w], 1)] = s.w;
}

// ---------------- tensor-core GEMM -------------------------------------------
// h' = (X@W)*dinv[row], bf16 out. Single-stage: full X tile + full W staged
// once (max MLP on the DRAM stream), one barrier, sync-free MMA loop.
__device__ __forceinline__ void mma16816(float* c, const uint32_t* a, const uint32_t* b) {
    asm volatile(
        "mma.sync.aligned.m16n8k16.row.col.f32.bf16.bf16.f32 "
        "{%0,%1,%2,%3}, {%4,%5,%6,%7}, {%8,%9}, {%0,%1,%2,%3};"
        : "+f"(c[0]), "+f"(c[1]), "+f"(c[2]), "+f"(c[3])
        : "r"(a[0]), "r"(a[1]), "r"(a[2]), "r"(a[3]), "r"(b[0]), "r"(b[1]));
}

template <int K, typename TIN>
__global__ void __launch_bounds__(256)
k_gemm_tc(const TIN* __restrict__ X, const float* __restrict__ W,
          __nv_bfloat16* __restrict__ Hs) {
    constexpr int XS = K + 8;   // bf16 row stride: 136/72 -> conflict-free ldmatrix
    __shared__ __align__(16) __nv_bfloat16 Xs[128][XS];
    __shared__ __align__(16) __nv_bfloat16 Ws[K][72];

    const int t = threadIdx.x;
    const int lane = t & 31, wid = t >> 5;
    const int wm = (wid & 3) * 32;      // warp row base
    const int wn = (wid >> 2) * 32;     // warp col base
    const int row0 = blockIdx.x * 128;

    // stage full X tile (128 x K) as bf16, 16B-granularity loads
    if constexpr (sizeof(TIN) == 4) {
        #pragma unroll
        for (int i = t; i < 128 * (K / 4); i += 256) {
            int r = i / (K / 4), q = i % (K / 4);
            int gr = row0 + r;
            float4 xv = make_float4(0.f, 0.f, 0.f, 0.f);
            if (gr < N_NODES)
                xv = *reinterpret_cast<const float4*>(
                    &reinterpret_cast<const float*>(X)[(size_t)gr * K + q * 4]);
            __nv_bfloat162 lo = __float22bfloat162_rn(make_float2(xv.x, xv.y));
            __nv_bfloat162 hi = __float22bfloat162_rn(make_float2(xv.z, xv.w));
            uint2 st;
            st.x = *reinterpret_cast<unsigned*>(&lo);
            st.y = *reinterpret_cast<unsigned*>(&hi);
            *reinterpret_cast<uint2*>(&Xs[r][q * 4]) = st;
        }
    } else {
        #pragma unroll
        for (int i = t; i < 128 * (K / 8); i += 256) {
            int r = i / (K / 8), q = i % (K / 8);
            int gr = row0 + r;
            uint4 xv = make_uint4(0u, 0u, 0u, 0u);
            if (gr < N_NODES)
                xv = *reinterpret_cast<const uint4*>(
                    &reinterpret_cast<const __nv_bfloat16*>(X)[(size_t)gr * K + q * 8]);
            *reinterpret_cast<uint4*>(&Xs[r][q * 8]) = xv;
        }
    }
    // stage full W (K x 64), fp32 -> bf16
    #pragma unroll
    for (int i = t; i < K * 32; i += 256) {
        int k = i >> 5, n2 = i & 31;
        float2 wv = *reinterpret_cast<const float2*>(&W[(size_t)k * 64 + n2 * 2]);
        *reinterpret_cast<__nv_bfloat162*>(&Ws[k][n2 * 2]) = __float22bfloat162_rn(wv);
    }
    __syncthreads();

    float c[2][4][4] = {};

    #pragma unroll
    for (int ks = 0; ks < K / 16; ks++) {
        const int kk = ks * 16;
        uint32_t a[2][4], b[4][2];
        #pragma unroll
        for (int mi = 0; mi < 2; mi++) {
            uint32_t addr = (uint32_t)__cvta_generic_to_shared(
                &Xs[wm + mi * 16 + (lane & 15)][kk + (lane >> 4) * 8]);
            asm volatile("ldmatrix.sync.aligned.m8n8.x4.shared.b16 {%0,%1,%2,%3}, [%4];"
                : "=r"(a[mi][0]), "=r"(a[mi][1]), "=r"(a[mi][2]), "=r"(a[mi][3])
                : "r"(addr));
        }
        #pragma unroll
        for (int ni = 0; ni < 4; ni++) {
            uint32_t addr = (uint32_t)__cvta_generic_to_shared(
                &Ws[kk + (lane & 15)][wn + ni * 8]);
            asm volatile("ldmatrix.sync.aligned.m8n8.x2.trans.shared.b16 {%0,%1}, [%2];"
                : "=r"(b[ni][0]), "=r"(b[ni][1]) : "r"(addr));
        }
        #pragma unroll
        for (int mi = 0; mi < 2; mi++)
            #pragma unroll
            for (int ni = 0; ni < 4; ni++)
                mma16816(c[mi][ni], a[mi], b[ni]);
    }

    // epilogue: scale rows by dinv, convert to bf16, store pairs
    #pragma unroll
    for (int mi = 0; mi < 2; mi++) {
        int r0 = row0 + wm + mi * 16 + (lane >> 2);
        int r1 = r0 + 8;
        float dv0 = (r0 < N_NODES) ? g_dinv[r0] : 0.f;
        float dv1 = (r1 < N_NODES) ? g_dinv[r1] : 0.f;
        #pragma unroll
        for (int ni = 0; ni < 4; ni++) {
            int col = wn + ni * 8 + (lane & 3) * 2;
            if (r0 < N_NODES) {
                __nv_bfloat162 p = __float22bfloat162_rn(
                    make_float2(c[mi][ni][0] * dv0, c[mi][ni][1] * dv0));
                *reinterpret_cast<__nv_bfloat162*>(&Hs[(size_t)r0 * 64 + col]) = p;
            }
            if (r1 < N_NODES) {
                __nv_bfloat162 p = __float22bfloat162_rn(
                    make_float2(c[mi][ni][2] * dv1, c[mi][ni][3] * dv1));
                *reinterpret_cast<__nv_bfloat162*>(&Hs[(size_t)r1 * 64 + col]) = p;
            }
        }
    }
}

// ---------------- pull aggregation helpers -----------------------------------
__device__ __forceinline__ void acc_bf8(float* a, uint4 v) {
    float2 f;
    f = __bfloat1622float2(*reinterpret_cast<__nv_bfloat162*>(&v.x)); a[0] += f.x; a[1] += f.y;
    f = __bfloat1622float2(*reinterpret_cast<__nv_bfloat162*>(&v.y)); a[2] += f.x; a[3] += f.y;
    f = __bfloat1622float2(*reinterpret_cast<__nv_bfloat162*>(&v.z)); a[4] += f.x; a[5] += f.y;
    f = __bfloat1622float2(*reinterpret_cast<__nv_bfloat162*>(&v.w)); a[6] += f.x; a[7] += f.y;
}

__device__ __forceinline__ uint4 hadd2x4(uint4 x, uint4 y) {
    uint4 r;
    __nv_bfloat162 h;
    h = __hadd2(*reinterpret_cast<__nv_bfloat162*>(&x.x),
                *reinterpret_cast<__nv_bfloat162*>(&y.x));
    r.x = *reinterpret_cast<unsigned*>(&h);
    h = __hadd2(*reinterpret_cast<__nv_bfloat162*>(&x.y),
                *reinterpret_cast<__nv_bfloat162*>(&y.y));
    r.y = *reinterpret_cast<unsigned*>(&h);
    h = __hadd2(*reinterpret_cast<__nv_bfloat162*>(&x.z),
                *reinterpret_cast<__nv_bfloat162*>(&y.z));
    r.z = *reinterpret_cast<unsigned*>(&h);
    h = __hadd2(*reinterpret_cast<__nv_bfloat162*>(&x.w),
                *reinterpret_cast<__nv_bfloat162*>(&y.w));
    r.w = *reinterpret_cast<unsigned*>(&h);
    return r;
}

// 8 threads/node, shuffle-broadcast indices; pairwise bf16 add then fp32 acc.
__device__ __forceinline__ void gather_node(const uint4* hp, int node, int sub,
                                            int gbase, unsigned gmask, float* a) {
    int beg = g_off[node];
    int end = g_off[node + 1];
    acc_bf8(a, hp[(size_t)node * 8 + sub]);   // self term
    int j = beg;
    for (; j + 8 <= end; j += 8) {
        int idx = g_ssrc[j + sub];
        #pragma unroll
        for (int t = 0; t < 4; t++) {
            int s0 = __shfl_sync(gmask, idx, gbase + 2 * t, 32);
            int s1 = __shfl_sync(gmask, idx, gbase + 2 * t + 1, 32);
            uint4 v0 = hp[(size_t)s0 * 8 + sub];
            uint4 v1 = hp[(size_t)s1 * 8 + sub];
            acc_bf8(a, hadd2x4(v0, v1));      // one bf16 rounding per pair
        }
    }
    if (j < end) {
        int n8 = end - j;
        int idx = (sub < n8) ? g_ssrc[j + sub] : 0;
        #pragma unroll 7
        for (int t = 0; t < 7; t++) {
            if (t >= n8) break;
            int s = __shfl_sync(gmask, idx, gbase + t, 32);
            acc_bf8(a, hp[(size_t)s * 8 + sub]);
        }
    }
}

// layer-1 gather: x2 = relu(dinv[d]*(h'[d] + sum h'[src]) + b1), bf16 out
__global__ void k_gather_x2(const __nv_bfloat16* __restrict__ h,
                            const float* __restrict__ b1,
                            __nv_bfloat16* __restrict__ out) {
    int tid = blockIdx.x * blockDim.x + threadIdx.x;
    int node = tid >> 3;
    if (node >= N_NODES) return;
    const int lane = threadIdx.x & 31;
    const int sub = lane & 7;
    const int gbase = lane & 24;
    const unsigned gmask = 0xFFu << gbase;
    const uint4* hp = reinterpret_cast<const uint4*>(h);

    float a[8] = {};
    gather_node(hp, node, sub, gbase, gmask, a);

    float dv = g_dinv[node];
    float v[8];
    #pragma unroll
    for (int j = 0; j < 8; j++)
        v[j] = fmaxf(a[j] * dv + __ldg(&b1[sub * 8 + j]), 0.f);

    __nv_bfloat162 p0 = __float22bfloat162_rn(make_float2(v[0], v[1]));
    __nv_bfloat162 p1 = __float22bfloat162_rn(make_float2(v[2], v[3]));
    __nv_bfloat162 p2 = __float22bfloat162_rn(make_float2(v[4], v[5]));
    __nv_bfloat162 p3 = __float22bfloat162_rn(make_float2(v[6], v[7]));
    uint4 st;
    st.x = *reinterpret_cast<unsigned*>(&p0);
    st.y = *reinterpret_cast<unsigned*>(&p1);
    st.z = *reinterpret_cast<unsigned*>(&p2);
    st.w = *reinterpret_cast<unsigned*>(&p3);
    *reinterpret_cast<uint4*>(&out[(size_t)node * 64 + sub * 8]) = st;
}

// layer-2 gather fused with mean-pool accumulation
__global__ void k_gather_pool(const __nv_bfloat16* __restrict__ h,
                              const int* __restrict__ batch,
                              const float* __restrict__ b2) {
    __shared__ float sacc[8][64];
    int tid = blockIdx.x * blockDim.x + threadIdx.x;
    int node = tid >> 3;                       // 3125 full blocks x 32 nodes
    const int lane = threadIdx.x & 31;
    const int wid = threadIdx.x >> 5;
    const int sub = lane & 7;
    const int gbase = lane & 24;
    const unsigned gmask = 0xFFu << gbase;
    const uint4* hp = reinterpret_cast<const uint4*>(h);

    float a[8] = {};
    gather_node(hp, node, sub, gbase, gmask, a);

    float dv = g_dinv[node];
    float v[8];
    #pragma unroll
    for (int j = 0; j < 8; j++)
        v[j] = fmaxf(a[j] * dv + __ldg(&b2[sub * 8 + j]), 0.f);

    int n0 = node & ~31;
    int bt0 = batch[n0];
    bool uniform = (bt0 == batch[n0 + 31]);

    if (uniform) {
        #pragma unroll
        for (int j = 0; j < 8; j++) {
            v[j] += __shfl_xor_sync(0xFFFFFFFFu, v[j], 8);
            v[j] += __shfl_xor_sync(0xFFFFFFFFu, v[j], 16);
        }
        if (lane < 8) {
            #pragma unroll
            for (int j = 0; j < 8; j++) sacc[wid][lane * 8 + j] = v[j];
        }
        __syncthreads();
        if (threadIdx.x < 64) {
            float s = 0.f;
            #pragma unroll
            for (int w = 0; w < 8; w++) s += sacc[w][threadIdx.x];
            atomicAdd(&g_gsum[bt0 * 64 + threadIdx.x], s);
        }
    } else {
        int bt = batch[node];
        #pragma unroll
        for (int j = 0; j < 8; j++)
            atomicAdd(&g_gsum[bt * 64 + sub * 8 + j], v[j]);
        __syncthreads();   // keep barrier count uniform
    }
}

// ---------------- head --------------------------------------------------------
__global__ void k_head(const int* __restrict__ batch,
                       const float* __restrict__ linW, const float* __restrict__ linb,
                       float* __restrict__ out) {
    int g = threadIdx.x;
    if (g >= N_GRAPHS) return;
    int lo = 0, hi = N_NODES;
    while (lo < hi) { int m = (lo + hi) >> 1; if (batch[m] < g) lo = m + 1; else hi = m; }
    int s0 = lo;
    lo = s0; hi = N_NODES;
    while (lo < hi) { int m = (lo + hi) >> 1; if (batch[m] < g + 1) lo = m + 1; else hi = m; }
    float cnt = (float)(lo - s0);
    float inv = 1.0f / fmaxf(cnt, 1.0f);

    float logits[N_CLASSES];
#pragma unroll
    for (int c = 0; c < N_CLASSES; c++) logits[c] = linb[c];
    for (int f = 0; f < HIDDEN; f++) {
        float p = g_gsum[g * HIDDEN + f] * inv;
#pragma unroll
        for (int c = 0; c < N_CLASSES; c++) logits[c] += p * linW[f * N_CLASSES + c];
    }
    float m = logits[0];
#pragma unroll
    for (int c = 1; c < N_CLASSES; c++) m = fmaxf(m, logits[c]);
    float s = 0.f;
#pragma unroll
    for (int c = 0; c < N_CLASSES; c++) s += expf(logits[c] - m);
    float l = logf(s) + m;
#pragma unroll
    for (int c = 0; c < N_CLASSES; c++) out[g * N_CLASSES + c] = logits[c] - l;
}

// ---------------- launch ------------------------------------------------------
extern "C" void kernel_launch(void* const* d_in, const int* in_sizes, int n_in,
                              void* d_out, int out_size) {
    const float* x     = (const float*)d_in[0];
    const int*   ei    = (const int*)d_in[1];
    const int*   batch = (const int*)d_in[2];
    const float* W1    = (const float*)d_in[3];
    const float* b1    = (const float*)d_in[4];
    const float* W2    = (const float*)d_in[5];
    const float* b2    = (const float*)d_in[6];
    const float* linW  = (const float*)d_in[7];
    const float* linb  = (const float*)d_in[8];
    float* out = (float*)d_out;

    const int* src = ei;
    const int* dst = ei + N_EDGES;

    __nv_bfloat16 *p_h, *p_x2;
    cudaGetSymbolAddress((void**)&p_h, g_h);
    cudaGetSymbolAddress((void**)&p_x2, g_x2);

    const int NT = 256;
    const int edge4Blocks = (N_EDGES / 4 + NT - 1) / NT;
    const int gemmBlocks = (N_NODES + 127) / 128;
    const int gatherBlocks = (N_NODES * 8 + NT - 1) / NT;

    k_zero<<<NBLK, NT>>>();
    k_hist<<<edge4Blocks, NT>>>(dst);
    k_scan_local<<<NBLK, 256>>>();                               // also computes dinv
    k_gemm_tc<D_FEAT, float><<<gemmBlocks, NT>>>(x, W1, p_h);    // profiled slot
    k_finalize<<<NBLK, NT>>>();                                  // self-contained prefix
    k_fill<<<edge4Blocks, NT>>>(src, dst);
    k_gather_x2<<<gatherBlocks, NT>>>(p_h, b1, p_x2);
    k_gemm_tc<HIDDEN, __nv_bfloat16><<<gemmBlocks, NT>>>(p_x2, W2, p_h);
    k_gather_pool<<<gatherBlocks, NT>>>(p_h, batch, b2);
    k_head<<<1, N_GRAPHS>>>(batch, linW, linb, out);
}

// round 17
// speedup vs baseline: 1.1249x; 1.0424x over previous
#include <cuda_runtime.h>
#include <cuda_bf16.h>
#include <cuda_fp16.h>
#include <cuda_fp8.h>
#include <math.h>
#include <stdint.h>

#define N_NODES  100000
#define N_EDGES  3200000
#define D_FEAT   128
#define HIDDEN   64
#define N_GRAPHS 64
#define N_CLASSES 10
#define NBLK     391   // ceil(N_NODES/256)

// ---------------- scratch (device globals; no allocation allowed) -----------
__device__ __align__(16) float g_dinv[N_NODES];
__device__ __align__(16) unsigned char g_h8[N_NODES * HIDDEN];  // h' as e4m3
__device__ __align__(16) __nv_bfloat16 g_x2[N_NODES * HIDDEN];  // relu(agg1+b1)
__device__ __align__(16) float g_gsum[N_GRAPHS * HIDDEN];
// CSR scratch
__device__ int g_cnt[N_NODES];
__device__ int g_incl[N_NODES];
__device__ int g_bsum[NBLK];
__device__ int g_off[N_NODES + 1];
__device__ int g_cur[N_NODES];
__device__ __align__(16) int g_ssrc[N_EDGES];

// ---------------- zero + CSR build -------------------------------------------
__global__ void k_zero() {
    int i = blockIdx.x * blockDim.x + threadIdx.x;
    if (i < N_NODES) g_cnt[i] = 0;
    if (i < N_GRAPHS * HIDDEN) g_gsum[i] = 0.f;
}

// 4 edges per thread via int4
__global__ void k_hist(const int* __restrict__ dst) {
    int e4 = blockIdx.x * blockDim.x + threadIdx.x;
    if (e4 * 4 >= N_EDGES) return;
    int4 d = *reinterpret_cast<const int4*>(dst + e4 * 4);
    atomicAdd(&g_cnt[d.x], 1);
    atomicAdd(&g_cnt[d.y], 1);
    atomicAdd(&g_cnt[d.z], 1);
    atomicAdd(&g_cnt[d.w], 1);
}

// local inclusive scan per 256-block; also computes dinv (cnt already loaded)
__global__ void k_scan_local() {
    __shared__ int sm[256];
    int i = blockIdx.x * 256 + threadIdx.x;
    int v = (i < N_NODES) ? g_cnt[i] : 0;
    if (i < N_NODES) g_dinv[i] = rsqrtf((float)(v + 1));   // +1 self loop
    sm[threadIdx.x] = v;
    __syncthreads();
    #pragma unroll
    for (int ofs = 1; ofs < 256; ofs <<= 1) {
        int t = (threadIdx.x >= ofs) ? sm[threadIdx.x - ofs] : 0;
        __syncthreads();
        sm[threadIdx.x] += t;
        __syncthreads();
    }
    if (i < N_NODES) g_incl[i] = sm[threadIdx.x];
    if (threadIdx.x == 255) g_bsum[blockIdx.x] = sm[255];
}

// offsets + cursors; each block reduces its own prefix of the 391 block sums
__global__ void k_finalize() {
    __shared__ int part[8];
    __shared__ int basesh;
    const int t = threadIdx.x;
    const int lane = t & 31, wid = t >> 5;
    const int b = blockIdx.x;

    int s = 0;
    for (int i = t; i < b; i += 256) s += g_bsum[i];
    #pragma unroll
    for (int o = 16; o; o >>= 1) s += __shfl_xor_sync(0xFFFFFFFFu, s, o);
    if (lane == 0) part[wid] = s;
    __syncthreads();
    if (t == 0) {
        int tot = 0;
        #pragma unroll
        for (int w = 0; w < 8; w++) tot += part[w];
        basesh = tot;
        if (b == 0) g_off[N_NODES] = N_EDGES;
    }
    __syncthreads();
    int base = basesh;

    int i = b * 256 + t;
    if (i >= N_NODES) return;
    int c = g_cnt[i];
    int o = base + g_incl[i] - c;   // exclusive global offset
    g_off[i] = o;
    g_cur[i] = o;
}

// 4 edges per thread via int4
__global__ void k_fill(const int* __restrict__ src, const int* __restrict__ dst) {
    int e4 = blockIdx.x * blockDim.x + threadIdx.x;
    if (e4 * 4 >= N_EDGES) return;
    int4 s = *reinterpret_cast<const int4*>(src + e4 * 4);
    int4 d = *reinterpret_cast<const int4*>(dst + e4 * 4);
    g_ssrc[atomicAdd(&g_cur[d.x], 1)] = s.x;
    g_ssrc[atomicAdd(&g_cur[d.y], 1)] = s.y;
    g_ssrc[atomicAdd(&g_cur[d.z], 1)] = s.z;
    g_ssrc[atomicAdd(&g_cur[d.w], 1)] = s.w;
}

// ---------------- tensor-core GEMM -------------------------------------------
// h' = (X@W)*dinv[row], e4m3 out. Single-stage: full X tile + full W staged
// once (max MLP on the DRAM stream), one barrier, sync-free MMA loop.
__device__ __forceinline__ void mma16816(float* c, const uint32_t* a, const uint32_t* b) {
    asm volatile(
        "mma.sync.aligned.m16n8k16.row.col.f32.bf16.bf16.f32 "
        "{%0,%1,%2,%3}, {%4,%5,%6,%7}, {%8,%9}, {%0,%1,%2,%3};"
        : "+f"(c[0]), "+f"(c[1]), "+f"(c[2]), "+f"(c[3])
        : "r"(a[0]), "r"(a[1]), "r"(a[2]), "r"(a[3]), "r"(b[0]), "r"(b[1]));
}

template <int K, typename TIN>
__global__ void __launch_bounds__(256)
k_gemm_tc(const TIN* __restrict__ X, const float* __restrict__ W,
          unsigned char* __restrict__ H8) {
    constexpr int XS = K + 8;   // bf16 row stride: 136/72 -> conflict-free ldmatrix
    __shared__ __align__(16) __nv_bfloat16 Xs[128][XS];
    __shared__ __align__(16) __nv_bfloat16 Ws[K][72];

    const int t = threadIdx.x;
    const int lane = t & 31, wid = t >> 5;
    const int wm = (wid & 3) * 32;      // warp row base
    const int wn = (wid >> 2) * 32;     // warp col base
    const int row0 = blockIdx.x * 128;

    // stage full X tile (128 x K) as bf16, 16B-granularity loads
    if constexpr (sizeof(TIN) == 4) {
        #pragma unroll
        for (int i = t; i < 128 * (K / 4); i += 256) {
            int r = i / (K / 4), q = i % (K / 4);
            int gr = row0 + r;
            float4 xv = make_float4(0.f, 0.f, 0.f, 0.f);
            if (gr < N_NODES)
                xv = *reinterpret_cast<const float4*>(
                    &reinterpret_cast<const float*>(X)[(size_t)gr * K + q * 4]);
            __nv_bfloat162 lo = __float22bfloat162_rn(make_float2(xv.x, xv.y));
            __nv_bfloat162 hi = __float22bfloat162_rn(make_float2(xv.z, xv.w));
            uint2 st;
            st.x = *reinterpret_cast<unsigned*>(&lo);
            st.y = *reinterpret_cast<unsigned*>(&hi);
            *reinterpret_cast<uint2*>(&Xs[r][q * 4]) = st;
        }
    } else {
        #pragma unroll
        for (int i = t; i < 128 * (K / 8); i += 256) {
            int r = i / (K / 8), q = i % (K / 8);
            int gr = row0 + r;
            uint4 xv = make_uint4(0u, 0u, 0u, 0u);
            if (gr < N_NODES)
                xv = *reinterpret_cast<const uint4*>(
                    &reinterpret_cast<const __nv_bfloat16*>(X)[(size_t)gr * K + q * 8]);
            *reinterpret_cast<uint4*>(&Xs[r][q * 8]) = xv;
        }
    }
    // stage full W (K x 64), fp32 -> bf16
    #pragma unroll
    for (int i = t; i < K * 32; i += 256) {
        int k = i >> 5, n2 = i & 31;
        float2 wv = *reinterpret_cast<const float2*>(&W[(size_t)k * 64 + n2 * 2]);
        *reinterpret_cast<__nv_bfloat162*>(&Ws[k][n2 * 2]) = __float22bfloat162_rn(wv);
    }
    __syncthreads();

    float c[2][4][4] = {};

    #pragma unroll
    for (int ks = 0; ks < K / 16; ks++) {
        const int kk = ks * 16;
        uint32_t a[2][4], b[4][2];
        #pragma unroll
        for (int mi = 0; mi < 2; mi++) {
            uint32_t addr = (uint32_t)__cvta_generic_to_shared(
                &Xs[wm + mi * 16 + (lane & 15)][kk + (lane >> 4) * 8]);
            asm volatile("ldmatrix.sync.aligned.m8n8.x4.shared.b16 {%0,%1,%2,%3}, [%4];"
                : "=r"(a[mi][0]), "=r"(a[mi][1]), "=r"(a[mi][2]), "=r"(a[mi][3])
                : "r"(addr));
        }
        #pragma unroll
        for (int ni = 0; ni < 4; ni++) {
            uint32_t addr = (uint32_t)__cvta_generic_to_shared(
                &Ws[kk + (lane & 15)][wn + ni * 8]);
            asm volatile("ldmatrix.sync.aligned.m8n8.x2.trans.shared.b16 {%0,%1}, [%2];"
                : "=r"(b[ni][0]), "=r"(b[ni][1]) : "r"(addr));
        }
        #pragma unroll
        for (int mi = 0; mi < 2; mi++)
            #pragma unroll
            for (int ni = 0; ni < 4; ni++)
                mma16816(c[mi][ni], a[mi], b[ni]);
    }

    // epilogue: scale rows by dinv, convert to e4m3 pairs, store 2B each
    #pragma unroll
    for (int mi = 0; mi < 2; mi++) {
        int r0 = row0 + wm + mi * 16 + (lane >> 2);
        int r1 = r0 + 8;
        float dv0 = (r0 < N_NODES) ? g_dinv[r0] : 0.f;
        float dv1 = (r1 < N_NODES) ? g_dinv[r1] : 0.f;
        #pragma unroll
        for (int ni = 0; ni < 4; ni++) {
            int col = wn + ni * 8 + (lane & 3) * 2;
            if (r0 < N_NODES) {
                __nv_fp8x2_storage_t p = __nv_cvt_float2_to_fp8x2(
                    make_float2(c[mi][ni][0] * dv0, c[mi][ni][1] * dv0),
                    __NV_SATFINITE, __NV_E4M3);
                *reinterpret_cast<unsigned short*>(&H8[(size_t)r0 * 64 + col]) = p;
            }
            if (r1 < N_NODES) {
                __nv_fp8x2_storage_t p = __nv_cvt_float2_to_fp8x2(
                    make_float2(c[mi][ni][2] * dv1, c[mi][ni][3] * dv1),
                    __NV_SATFINITE, __NV_E4M3);
                *reinterpret_cast<unsigned short*>(&H8[(size_t)r1 * 64 + col]) = p;
            }
        }
    }
}

// ---------------- pull aggregation helpers -----------------------------------
__device__ __forceinline__ __half2 fp8x2_to_h2(unsigned short s) {
    __half2_raw r = __nv_cvt_fp8x2_to_halfraw2((__nv_fp8x2_storage_t)s, __NV_E4M3);
    return *reinterpret_cast<__half2*>(&r);
}

// accumulate one edge's 8 fp8 feats (uint2) into half2 acc[4]
__device__ __forceinline__ void acc_fp8(__half2* a, uint2 v) {
    a[0] = __hadd2(a[0], fp8x2_to_h2((unsigned short)(v.x)));
    a[1] = __hadd2(a[1], fp8x2_to_h2((unsigned short)(v.x >> 16)));
    a[2] = __hadd2(a[2], fp8x2_to_h2((unsigned short)(v.y)));
    a[3] = __hadd2(a[3], fp8x2_to_h2((unsigned short)(v.y >> 16)));
}

// 8 threads/node, shuffle-broadcast indices; fp16 accumulate of fp8 rows.
// Result (8 fp32 feats) written to out[8].
__device__ __forceinline__ void gather_node8(const uint2* hp, int node, int sub,
                                             int gbase, unsigned gmask, float* out) {
    int beg = g_off[node];
    int end = g_off[node + 1];
    uint2 selfv = hp[(size_t)node * 8 + sub];
    __half2 a[4];
    a[0] = fp8x2_to_h2((unsigned short)(selfv.x));
    a[1] = fp8x2_to_h2((unsigned short)(selfv.x >> 16));
    a[2] = fp8x2_to_h2((unsigned short)(selfv.y));
    a[3] = fp8x2_to_h2((unsigned short)(selfv.y >> 16));

    int j = beg;
    for (; j + 8 <= end; j += 8) {
        int idx = g_ssrc[j + sub];
        #pragma unroll
        for (int t = 0; t < 8; t++) {
            int s = __shfl_sync(gmask, idx, gbase + t, 32);
            acc_fp8(a, hp[(size_t)s * 8 + sub]);
        }
    }
    if (j < end) {
        int n8 = end - j;
        int idx = (sub < n8) ? g_ssrc[j + sub] : 0;
        #pragma unroll 7
        for (int t = 0; t < 7; t++) {
            if (t >= n8) break;
            int s = __shfl_sync(gmask, idx, gbase + t, 32);
            acc_fp8(a, hp[(size_t)s * 8 + sub]);
        }
    }

    #pragma unroll
    for (int q = 0; q < 4; q++) {
        float2 f = __half22float2(a[q]);
        out[q * 2 + 0] = f.x;
        out[q * 2 + 1] = f.y;
    }
}

// layer-1 gather: x2 = relu(dinv[d]*(h'[d] + sum h'[src]) + b1), bf16 out
__global__ void k_gather_x2(const unsigned char* __restrict__ h8,
                            const float* __restrict__ b1,
                            __nv_bfloat16* __restrict__ out) {
    int tid = blockIdx.x * blockDim.x + threadIdx.x;
    int node = tid >> 3;
    if (node >= N_NODES) return;
    const int lane = threadIdx.x & 31;
    const int sub = lane & 7;
    const int gbase = lane & 24;
    const unsigned gmask = 0xFFu << gbase;
    const uint2* hp = reinterpret_cast<const uint2*>(h8);

    float a[8];
    gather_node8(hp, node, sub, gbase, gmask, a);

    float dv = g_dinv[node];
    float v[8];
    #pragma unroll
    for (int j = 0; j < 8; j++)
        v[j] = fmaxf(a[j] * dv + __ldg(&b1[sub * 8 + j]), 0.f);

    __nv_bfloat162 p0 = __float22bfloat162_rn(make_float2(v[0], v[1]));
    __nv_bfloat162 p1 = __float22bfloat162_rn(make_float2(v[2], v[3]));
    __nv_bfloat162 p2 = __float22bfloat162_rn(make_float2(v[4], v[5]));
    __nv_bfloat162 p3 = __float22bfloat162_rn(make_float2(v[6], v[7]));
    uint4 st;
    st.x = *reinterpret_cast<unsigned*>(&p0);
    st.y = *reinterpret_cast<unsigned*>(&p1);
    st.z = *reinterpret_cast<unsigned*>(&p2);
    st.w = *reinterpret_cast<unsigned*>(&p3);
    *reinterpret_cast<uint4*>(&out[(size_t)node * 64 + sub * 8]) = st;
}

// layer-2 gather fused with mean-pool accumulation
__global__ void k_gather_pool(const unsigned char* __restrict__ h8,
                              const int* __restrict__ batch,
                              const float* __restrict__ b2) {
    __shared__ float sacc[8][64];
    int tid = blockIdx.x * blockDim.x + threadIdx.x;
    int node = tid >> 3;                       // 3125 full blocks x 32 nodes
    const int lane = threadIdx.x & 31;
    const int wid = threadIdx.x >> 5;
    const int sub = lane & 7;
    const int gbase = lane & 24;
    const unsigned gmask = 0xFFu << gbase;
    const uint2* hp = reinterpret_cast<const uint2*>(h8);

    float a[8];
    gather_node8(hp, node, sub, gbase, gmask, a);

    float dv = g_dinv[node];
    float v[8];
    #pragma unroll
    for (int j = 0; j < 8; j++)
        v[j] = fmaxf(a[j] * dv + __ldg(&b2[sub * 8 + j]), 0.f);

    int n0 = node & ~31;
    int bt0 = batch[n0];
    bool uniform = (bt0 == batch[n0 + 31]);

    if (uniform) {
        #pragma unroll
        for (int j = 0; j < 8; j++) {
            v[j] += __shfl_xor_sync(0xFFFFFFFFu, v[j], 8);
            v[j] += __shfl_xor_sync(0xFFFFFFFFu, v[j], 16);
        }
        if (lane < 8) {
            #pragma unroll
            for (int j = 0; j < 8; j++) sacc[wid][lane * 8 + j] = v[j];
        }
        __syncthreads();
        if (threadIdx.x < 64) {
            float s = 0.f;
            #pragma unroll
            for (int w = 0; w < 8; w++) s += sacc[w][threadIdx.x];
            atomicAdd(&g_gsum[bt0 * 64 + threadIdx.x], s);
        }
    } else {
        int bt = batch[node];
        #pragma unroll
        for (int j = 0; j < 8; j++)
            atomicAdd(&g_gsum[bt * 64 + sub * 8 + j], v[j]);
        __syncthreads();   // keep barrier count uniform
    }
}

// ---------------- head --------------------------------------------------------
__global__ void k_head(const int* __restrict__ batch,
                       const float* __restrict__ linW, const float* __restrict__ linb,
                       float* __restrict__ out) {
    int g = threadIdx.x;
    if (g >= N_GRAPHS) return;
    int lo = 0, hi = N_NODES;
    while (lo < hi) { int m = (lo + hi) >> 1; if (batch[m] < g) lo = m + 1; else hi = m; }
    int s0 = lo;
    lo = s0; hi = N_NODES;
    while (lo < hi) { int m = (lo + hi) >> 1; if (batch[m] < g + 1) lo = m + 1; else hi = m; }
    float cnt = (float)(lo - s0);
    float inv = 1.0f / fmaxf(cnt, 1.0f);

    float logits[N_CLASSES];
#pragma unroll
    for (int c = 0; c < N_CLASSES; c++) logits[c] = linb[c];
    for (int f = 0; f < HIDDEN; f++) {
        float p = g_gsum[g * HIDDEN + f] * inv;
#pragma unroll
        for (int c = 0; c < N_CLASSES; c++) logits[c] += p * linW[f * N_CLASSES + c];
    }
    float m = logits[0];
#pragma unroll
    for (int c = 1; c < N_CLASSES; c++) m = fmaxf(m, logits[c]);
    float s = 0.f;
#pragma unroll
    for (int c = 0; c < N_CLASSES; c++) s += expf(logits[c] - m);
    float l = logf(s) + m;
#pragma unroll
    for (int c = 0; c < N_CLASSES; c++) out[g * N_CLASSES + c] = logits[c] - l;
}

// ---------------- launch ------------------------------------------------------
extern "C" void kernel_launch(void* const* d_in, const int* in_sizes, int n_in,
                              void* d_out, int out_size) {
    const float* x     = (const float*)d_in[0];
    const int*   ei    = (const int*)d_in[1];
    const int*   batch = (const int*)d_in[2];
    const float* W1    = (const float*)d_in[3];
    const float* b1    = (const float*)d_in[4];
    const float* W2    = (const float*)d_in[5];
    const float* b2    = (const float*)d_in[6];
    const float* linW  = (const float*)d_in[7];
    const float* linb  = (const float*)d_in[8];
    float* out = (float*)d_out;

    const int* src = ei;
    const int* dst = ei + N_EDGES;

    unsigned char* p_h8;
    __nv_bfloat16* p_x2;
    cudaGetSymbolAddress((void**)&p_h8, g_h8);
    cudaGetSymbolAddress((void**)&p_x2, g_x2);

    const int NT = 256;
    const int edge4Blocks = (N_EDGES / 4 + NT - 1) / NT;
    const int gemmBlocks = (N_NODES + 127) / 128;
    const int gatherBlocks = (N_NODES * 8 + NT - 1) / NT;

    k_zero<<<NBLK, NT>>>();
    k_hist<<<edge4Blocks, NT>>>(dst);
    k_scan_local<<<NBLK, 256>>>();                               // also computes dinv
    k_gemm_tc<D_FEAT, float><<<gemmBlocks, NT>>>(x, W1, p_h8);   // profiled slot
    k_finalize<<<NBLK, NT>>>();                                  // self-contained prefix
    k_fill<<<edge4Blocks, NT>>>(src, dst);
    k_gather_x2<<<gatherBlocks, NT>>>(p_h8, b1, p_x2);
    k_gemm_tc<HIDDEN, __nv_bfloat16><<<gemmBlocks, NT>>>(p_x2, W2, p_h8);
    k_gather_pool<<<gatherBlocks, NT>>>(p_h8, batch, b2);
    k_head<<<1, N_GRAPHS>>>(batch, linW, linb, out);
}